// round 1
// baseline (speedup 1.0000x reference)
#include <cuda_runtime.h>
#include <cstdint>

// Problem constants
#define BB 512
#define SS 200
#define DD 512
#define HH 8
#define DHH 64
#define MM (BB*SS)          // 102400 rows

// ---------------------------------------------------------------------------
// Scratch (device globals; no allocations anywhere)
// ---------------------------------------------------------------------------
__device__ float g_h   [(size_t)MM * DD];        // LayerNormed input (residual + GEMM A)
__device__ float g_qkv [(size_t)MM * 3 * DD];    // [M, 1536] : q | k | v
__device__ float g_kv  [(size_t)BB * HH * DHH * DHH];
__device__ float g_ctx [(size_t)MM * DD];
__device__ float g_o   [(size_t)MM * DD];
__device__ float g_Wqkv[(size_t)DD * 3 * DD];    // [512][1536] packed weights
__device__ float g_bqkv[3 * DD];

// ---------------------------------------------------------------------------
// Kernel 0: pack Wq|Wk|Wv -> [K=512][N=1536], biases
// ---------------------------------------------------------------------------
__global__ void pack_w(const float* __restrict__ Wq, const float* __restrict__ Wk,
                       const float* __restrict__ Wv, const float* __restrict__ bq,
                       const float* __restrict__ bk, const float* __restrict__ bv) {
    int idx = blockIdx.x * 256 + threadIdx.x;
    if (idx < DD * DD) {
        int k = idx >> 9, n = idx & 511;
        g_Wqkv[k * 1536 + n]        = Wq[idx];
        g_Wqkv[k * 1536 + 512 + n]  = Wk[idx];
        g_Wqkv[k * 1536 + 1024 + n] = Wv[idx];
    }
    if (idx < 512) {
        g_bqkv[idx]        = bq[idx];
        g_bqkv[512 + idx]  = bk[idx];
        g_bqkv[1024 + idx] = bv[idx];
    }
}

// ---------------------------------------------------------------------------
// Block reduce (128 threads, 2 values)
// ---------------------------------------------------------------------------
__device__ __forceinline__ void block_reduce2_128(float& a, float& b) {
#pragma unroll
    for (int o = 16; o > 0; o >>= 1) {
        a += __shfl_xor_sync(0xffffffffu, a, o);
        b += __shfl_xor_sync(0xffffffffu, b, o);
    }
    __shared__ float sa[4], sb[4];
    int w = threadIdx.x >> 5, l = threadIdx.x & 31;
    if (l == 0) { sa[w] = a; sb[w] = b; }
    __syncthreads();
    a = sa[0] + sa[1] + sa[2] + sa[3];
    b = sb[0] + sb[1] + sb[2] + sb[3];
}

// ---------------------------------------------------------------------------
// Kernel 1: h = LayerNorm(input + pos)   (one 128-thread block per row)
// ---------------------------------------------------------------------------
__global__ void add_ln(const float* __restrict__ x, const float* __restrict__ p,
                       const float* __restrict__ g, const float* __restrict__ b) {
    size_t row = blockIdx.x;
    int t = threadIdx.x;
    float4 xv = ((const float4*)x)[row * 128 + t];
    float4 pv = ((const float4*)p)[row * 128 + t];
    xv.x += pv.x; xv.y += pv.y; xv.z += pv.z; xv.w += pv.w;
    float s  = xv.x + xv.y + xv.z + xv.w;
    float ss = xv.x*xv.x + xv.y*xv.y + xv.z*xv.z + xv.w*xv.w;
    block_reduce2_128(s, ss);
    float mu  = s * (1.0f / 512.0f);
    float var = ss * (1.0f / 512.0f) - mu * mu;
    float rstd = rsqrtf(var + 1e-12f);
    float4 gv = ((const float4*)g)[t];
    float4 bv = ((const float4*)b)[t];
    float4 o;
    o.x = (xv.x - mu) * rstd * gv.x + bv.x;
    o.y = (xv.y - mu) * rstd * gv.y + bv.y;
    o.z = (xv.z - mu) * rstd * gv.z + bv.z;
    o.w = (xv.w - mu) * rstd * gv.w + bv.w;
    ((float4*)g_h)[row * 128 + t] = o;
}

// ---------------------------------------------------------------------------
// tf32 GEMM: C[M,N] = A[M,512] * B[512,N] + bias, block tile 128x64, K-tile 32
// mode 0: A=g_h, B=g_Wqkv, bias=g_bqkv, C=g_qkv, N=1536
// mode 1: A=g_ctx, B=extW, bias=extB,   C=g_o,   N=512
// ---------------------------------------------------------------------------
__device__ __forceinline__ uint32_t f2tf(float x) {
    uint32_t u; asm("cvt.rna.tf32.f32 %0, %1;" : "=r"(u) : "f"(x)); return u;
}

__global__ __launch_bounds__(256) void gemm_tf32(int mode, const float* __restrict__ extW,
                                                 const float* __restrict__ extB) {
    const float* A; const float* Bw; const float* bias; float* C; int N;
    if (mode == 0) { A = g_h;   Bw = g_Wqkv; bias = g_bqkv; C = g_qkv; N = 1536; }
    else           { A = g_ctx; Bw = extW;   bias = extB;   C = g_o;   N = 512;  }

    __shared__ float As[128 * 36];   // pad 36 -> conflict-free frag loads
    __shared__ float Bs[32 * 68];    // pad 68

    int tid  = threadIdx.x;
    int warp = tid >> 5, lane = tid & 31;
    int wm = warp >> 2, wn = warp & 3;          // 2 x 4 warp grid
    int gid = lane >> 2, tig = lane & 3;
    int m0 = blockIdx.y * 128, n0 = blockIdx.x * 64;

    float acc[4][2][4];
#pragma unroll
    for (int i = 0; i < 4; i++)
#pragma unroll
        for (int j = 0; j < 2; j++)
#pragma unroll
            for (int k = 0; k < 4; k++) acc[i][j][k] = 0.0f;

    for (int kt = 0; kt < 16; ++kt) {
        // A tile: 128 x 32
#pragma unroll
        for (int i = 0; i < 4; i++) {
            int q = tid + i * 256;
            int r = q >> 3, qc = q & 7;
            float4 v = *(const float4*)(A + (size_t)(m0 + r) * 512 + kt * 32 + qc * 4);
            uint4 u; u.x = f2tf(v.x); u.y = f2tf(v.y); u.z = f2tf(v.z); u.w = f2tf(v.w);
            *(uint4*)(As + r * 36 + qc * 4) = u;
        }
        // B tile: 32 x 64
#pragma unroll
        for (int i = 0; i < 2; i++) {
            int q = tid + i * 256;
            int kr = q >> 4, nc = q & 15;
            float4 v = *(const float4*)(Bw + (size_t)(kt * 32 + kr) * N + n0 + nc * 4);
            uint4 u; u.x = f2tf(v.x); u.y = f2tf(v.y); u.z = f2tf(v.z); u.w = f2tf(v.w);
            *(uint4*)(Bs + kr * 68 + nc * 4) = u;
        }
        __syncthreads();

#pragma unroll
        for (int k8 = 0; k8 < 4; k8++) {
            uint32_t bf[2][2];
#pragma unroll
            for (int nt = 0; nt < 2; nt++) {
                int col = wn * 16 + nt * 8 + gid;
                bf[nt][0] = __float_as_uint(Bs[(k8 * 8 + tig) * 68 + col]);
                bf[nt][1] = __float_as_uint(Bs[(k8 * 8 + tig + 4) * 68 + col]);
            }
#pragma unroll
            for (int mt = 0; mt < 4; mt++) {
                int rb = wm * 64 + mt * 16;
                uint32_t a0 = __float_as_uint(As[(rb + gid) * 36 + k8 * 8 + tig]);
                uint32_t a1 = __float_as_uint(As[(rb + 8 + gid) * 36 + k8 * 8 + tig]);
                uint32_t a2 = __float_as_uint(As[(rb + gid) * 36 + k8 * 8 + tig + 4]);
                uint32_t a3 = __float_as_uint(As[(rb + 8 + gid) * 36 + k8 * 8 + tig + 4]);
#pragma unroll
                for (int nt = 0; nt < 2; nt++) {
                    asm volatile(
                        "mma.sync.aligned.m16n8k8.row.col.f32.tf32.tf32.f32 "
                        "{%0,%1,%2,%3},{%4,%5,%6,%7},{%8,%9},{%0,%1,%2,%3};"
                        : "+f"(acc[mt][nt][0]), "+f"(acc[mt][nt][1]),
                          "+f"(acc[mt][nt][2]), "+f"(acc[mt][nt][3])
                        : "r"(a0), "r"(a1), "r"(a2), "r"(a3),
                          "r"(bf[nt][0]), "r"(bf[nt][1]));
                }
            }
        }
        __syncthreads();
    }

#pragma unroll
    for (int mt = 0; mt < 4; mt++)
#pragma unroll
        for (int nt = 0; nt < 2; nt++) {
            int row = m0 + wm * 64 + mt * 16 + gid;
            int col = n0 + wn * 16 + nt * 8 + 2 * tig;
            float b0 = bias[col], b1 = bias[col + 1];
            *(float2*)(C + (size_t)row * N + col) =
                make_float2(acc[mt][nt][0] + b0, acc[mt][nt][1] + b1);
            *(float2*)(C + (size_t)(row + 8) * N + col) =
                make_float2(acc[mt][nt][2] + b0, acc[mt][nt][3] + b1);
        }
}

// ---------------------------------------------------------------------------
// Kernel 3: ELU + per-head L2 normalize for q and k (in place). 1 warp / 64-row
// ---------------------------------------------------------------------------
__global__ void featmap() {
    int wid  = (blockIdx.x * blockDim.x + threadIdx.x) >> 5;
    int lane = threadIdx.x & 31;
    int which = wid & 1;             // 0 = q, 1 = k
    int h     = (wid >> 1) & 7;
    size_t m  = (size_t)(wid >> 4);
    float* ptr = g_qkv + m * 1536 + which * 512 + h * 64;
    float2 v = *(float2*)(ptr + lane * 2);
    v.x = v.x > 0.0f ? v.x : expm1f(v.x);
    v.y = v.y > 0.0f ? v.y : expm1f(v.y);
    float ss = v.x * v.x + v.y * v.y;
#pragma unroll
    for (int o = 16; o > 0; o >>= 1) ss += __shfl_xor_sync(0xffffffffu, ss, o);
    float r = rsqrtf(ss);
    *(float2*)(ptr + lane * 2) = make_float2(v.x * r, v.y * r);
}

// ---------------------------------------------------------------------------
// Kernel 4: kv[b,h,d,e] = sum_s kn[s,d] * v[s,e]   (one block per (b,h))
// ---------------------------------------------------------------------------
__global__ __launch_bounds__(256) void kv_kernel() {
    int bh = blockIdx.x;
    int b = bh >> 3, h = bh & 7;
    __shared__ float kn_s[40 * 64];
    __shared__ float v_s [40 * 64];
    int tid = threadIdx.x;
    int d0 = (tid >> 4) << 2, e0 = (tid & 15) << 2;
    const float* base = g_qkv + (size_t)b * 200 * 1536 + h * 64;
    float acc[4][4];
#pragma unroll
    for (int i = 0; i < 4; i++)
#pragma unroll
        for (int j = 0; j < 4; j++) acc[i][j] = 0.0f;

    for (int st = 0; st < 5; ++st) {
        __syncthreads();
        for (int i = tid; i < 40 * 16; i += 256) {
            int r = i >> 4, nc = (i & 15) << 2;
            size_t off = (size_t)(st * 40 + r) * 1536 + nc;
            *(float4*)(kn_s + r * 64 + nc) = *(const float4*)(base + 512  + off);
            *(float4*)(v_s  + r * 64 + nc) = *(const float4*)(base + 1024 + off);
        }
        __syncthreads();
#pragma unroll 8
        for (int s = 0; s < 40; s++) {
            float4 kk = *(float4*)(kn_s + s * 64 + d0);
            float4 vv = *(float4*)(v_s  + s * 64 + e0);
            float ka[4] = {kk.x, kk.y, kk.z, kk.w};
            float va[4] = {vv.x, vv.y, vv.z, vv.w};
#pragma unroll
            for (int i = 0; i < 4; i++)
#pragma unroll
                for (int j = 0; j < 4; j++) acc[i][j] += ka[i] * va[j];
        }
    }
    float* o = g_kv + (size_t)bh * 4096;
#pragma unroll
    for (int i = 0; i < 4; i++)
        *(float4*)(o + (d0 + i) * 64 + e0) =
            make_float4(acc[i][0], acc[i][1], acc[i][2], acc[i][3]);
}

// ---------------------------------------------------------------------------
// Kernel 5: ctx[b,s,h,e] = (1/8) * sum_d qn[s,d] * kv[d,e]
// ---------------------------------------------------------------------------
__global__ __launch_bounds__(256) void ctx_kernel() {
    int bh = blockIdx.x;
    int b = bh >> 3, h = bh & 7;
    __shared__ float kvs[64 * 64];
    __shared__ float qns[64 * 68];
    int tid = threadIdx.x;
    for (int i = tid; i < 64 * 16; i += 256) {
        int d = i >> 4, nc = (i & 15) << 2;
        *(float4*)(kvs + d * 64 + nc) = *(const float4*)(g_kv + (size_t)bh * 4096 + d * 64 + nc);
    }
    const float* qbase = g_qkv + (size_t)b * 200 * 1536 + h * 64;
    float* obase = g_ctx + (size_t)b * 200 * 512 + h * 64;

    for (int c = 0; c < 4; c++) {
        int cs = min(64, 200 - c * 64);
        __syncthreads();
        for (int i = tid; i < cs * 16; i += 256) {
            int r = i >> 4, nc = (i & 15) << 2;
            *(float4*)(qns + r * 68 + nc) =
                *(const float4*)(qbase + (size_t)(c * 64 + r) * 1536 + nc);
        }
        __syncthreads();
        int sl = (tid >> 4) << 2, e0 = (tid & 15) << 2;
        if (sl < cs) {
            float acc[4][4];
#pragma unroll
            for (int i = 0; i < 4; i++)
#pragma unroll
                for (int j = 0; j < 4; j++) acc[i][j] = 0.0f;
#pragma unroll 8
            for (int d = 0; d < 64; d++) {
                float4 kv4 = *(float4*)(kvs + d * 64 + e0);
#pragma unroll
                for (int i = 0; i < 4; i++) {
                    float q = qns[(sl + i) * 68 + d];
                    acc[i][0] += q * kv4.x; acc[i][1] += q * kv4.y;
                    acc[i][2] += q * kv4.z; acc[i][3] += q * kv4.w;
                }
            }
#pragma unroll
            for (int i = 0; i < 4; i++)
                *(float4*)(obase + (size_t)(c * 64 + sl + i) * 512 + e0) =
                    make_float4(acc[i][0] * 0.125f, acc[i][1] * 0.125f,
                                acc[i][2] * 0.125f, acc[i][3] * 0.125f);
        }
    }
}

// ---------------------------------------------------------------------------
// Kernel 7: out = LayerNorm(g_o + g_h)
// ---------------------------------------------------------------------------
__global__ void final_ln(const float* __restrict__ g, const float* __restrict__ bv_,
                         float* __restrict__ out) {
    size_t row = blockIdx.x;
    int t = threadIdx.x;
    float4 ov = ((const float4*)g_o)[row * 128 + t];
    float4 hv = ((const float4*)g_h)[row * 128 + t];
    ov.x += hv.x; ov.y += hv.y; ov.z += hv.z; ov.w += hv.w;
    float s  = ov.x + ov.y + ov.z + ov.w;
    float ss = ov.x*ov.x + ov.y*ov.y + ov.z*ov.z + ov.w*ov.w;
    block_reduce2_128(s, ss);
    float mu  = s * (1.0f / 512.0f);
    float var = ss * (1.0f / 512.0f) - mu * mu;
    float rstd = rsqrtf(var + 1e-12f);
    float4 gv = ((const float4*)g)[t];
    float4 bb = ((const float4*)bv_)[t];
    float4 o;
    o.x = (ov.x - mu) * rstd * gv.x + bb.x;
    o.y = (ov.y - mu) * rstd * gv.y + bb.y;
    o.z = (ov.z - mu) * rstd * gv.z + bb.z;
    o.w = (ov.w - mu) * rstd * gv.w + bb.w;
    ((float4*)out)[row * 128 + t] = o;
}

// ---------------------------------------------------------------------------
// Launch
// ---------------------------------------------------------------------------
extern "C" void kernel_launch(void* const* d_in, const int* in_sizes, int n_in,
                              void* d_out, int out_size) {
    const float* input = (const float*)d_in[0];
    const float* pos   = (const float*)d_in[1];
    // d_in[2] = attention_mask (unused by LinMHA)
    const float* Wq = (const float*)d_in[3];
    const float* bq = (const float*)d_in[4];
    const float* Wk = (const float*)d_in[5];
    const float* bk = (const float*)d_in[6];
    const float* Wv = (const float*)d_in[7];
    const float* bv = (const float*)d_in[8];
    const float* Wd = (const float*)d_in[9];
    const float* bd = (const float*)d_in[10];
    const float* lng = (const float*)d_in[11];
    const float* lnb = (const float*)d_in[12];
    float* out = (float*)d_out;

    pack_w<<<1024, 256>>>(Wq, Wk, Wv, bq, bk, bv);
    add_ln<<<MM, 128>>>(input, pos, lng, lnb);
    gemm_tf32<<<dim3(24, 800), 256>>>(0, nullptr, nullptr);   // QKV
    featmap<<<204800, 256>>>();
    kv_kernel<<<4096, 256>>>();
    ctx_kernel<<<4096, 256>>>();
    gemm_tf32<<<dim3(8, 800), 256>>>(1, Wd, bd);              // output proj
    final_ln<<<MM, 128>>>(lng, lnb, out);
}

// round 3
// speedup vs baseline: 1.9842x; 1.9842x over previous
#include <cuda_runtime.h>
#include <cuda_fp16.h>
#include <cstdint>

#define BB 512
#define SS 200
#define DD 512
#define HH 8
#define DHH 64
#define MM (BB*SS)          // 102400 rows

// ---------------------------------------------------------------------------
// Scratch (device globals; no allocations anywhere)
// ---------------------------------------------------------------------------
__device__ float  g_h   [(size_t)MM * DD];        // fp32 LN(x) for residual
__device__ __half g_hh  [(size_t)MM * DD];        // fp16 LN(x) for GEMM A
__device__ float  g_qkv [(size_t)MM * 3 * DD];    // [M,1536] q|k|v (featmap fused)
__device__ float  g_kv  [(size_t)BB * HH * DHH * DHH];
__device__ __half g_ctxh[(size_t)MM * DD];        // fp16 ctx for GEMM2 A
__device__ float  g_o   [(size_t)MM * DD];
__device__ __half g_WtQKV[(size_t)3 * DD * DD];   // [1536][512] = W^T fp16
__device__ __half g_WtD  [(size_t)DD * DD];       // [512][512]  = Wd^T fp16
__device__ float  g_bqkv [3 * DD];

// ---------------------------------------------------------------------------
// Helpers
// ---------------------------------------------------------------------------
__device__ __forceinline__ uint32_t smem_u32(const void* p) {
    uint32_t a;
    asm("{ .reg .u64 t; cvta.to.shared.u64 t, %1; cvt.u32.u64 %0, t; }"
        : "=r"(a) : "l"(p));
    return a;
}
#define CPASYNC16(dst, src) \
    asm volatile("cp.async.cg.shared.global [%0], [%1], 16;" :: "r"(dst), "l"(src) : "memory")
#define CP_COMMIT() asm volatile("cp.async.commit_group;" ::: "memory")
#define CP_WAIT0()  asm volatile("cp.async.wait_group 0;" ::: "memory")
#define SWZ(o) ((o) ^ (((o) >> 3) & 0x70))

// ---------------------------------------------------------------------------
// Weight transpose + fp16: Wt[n][k] = fp16(W[k][n]). grid (16,16,4), block (32,8)
// ---------------------------------------------------------------------------
__global__ void pack_wt(const float* __restrict__ Wq, const float* __restrict__ Wk,
                        const float* __restrict__ Wv, const float* __restrict__ Wd) {
    __shared__ float t[32][33];
    int z = blockIdx.z;
    const float* W = z == 0 ? Wq : z == 1 ? Wk : z == 2 ? Wv : Wd;
    int x0 = blockIdx.x * 32, y0 = blockIdx.y * 32;
    int tx = threadIdx.x, ty = threadIdx.y;
#pragma unroll
    for (int i = 0; i < 32; i += 8)
        t[ty + i][tx] = W[(size_t)(y0 + ty + i) * 512 + x0 + tx];
    __syncthreads();
    __half* dst = (z < 3) ? (g_WtQKV + (size_t)z * 512 * 512) : g_WtD;
#pragma unroll
    for (int i = 0; i < 32; i += 8)
        dst[(size_t)(x0 + ty + i) * 512 + y0 + tx] = __float2half_rn(t[tx][ty + i]);
}

__global__ void pack_bias(const float* __restrict__ bq, const float* __restrict__ bk,
                          const float* __restrict__ bv) {
    int i = blockIdx.x * 256 + threadIdx.x;
    if (i < 512) { g_bqkv[i] = bq[i]; g_bqkv[512 + i] = bk[i]; g_bqkv[1024 + i] = bv[i]; }
}

// ---------------------------------------------------------------------------
// Block reduce (128 threads, 2 values)
// ---------------------------------------------------------------------------
__device__ __forceinline__ void block_reduce2_128(float& a, float& b) {
#pragma unroll
    for (int o = 16; o > 0; o >>= 1) {
        a += __shfl_xor_sync(0xffffffffu, a, o);
        b += __shfl_xor_sync(0xffffffffu, b, o);
    }
    __shared__ float sa[4], sb[4];
    int w = threadIdx.x >> 5, l = threadIdx.x & 31;
    if (l == 0) { sa[w] = a; sb[w] = b; }
    __syncthreads();
    a = sa[0] + sa[1] + sa[2] + sa[3];
    b = sb[0] + sb[1] + sb[2] + sb[3];
}

// ---------------------------------------------------------------------------
// h = LayerNorm(input + pos); write fp32 (residual) + fp16 (GEMM A)
// ---------------------------------------------------------------------------
__global__ void add_ln(const float* __restrict__ x, const float* __restrict__ p,
                       const float* __restrict__ g, const float* __restrict__ b) {
    size_t row = blockIdx.x;
    int t = threadIdx.x;
    float4 xv = ((const float4*)x)[row * 128 + t];
    float4 pv = ((const float4*)p)[row * 128 + t];
    xv.x += pv.x; xv.y += pv.y; xv.z += pv.z; xv.w += pv.w;
    float s  = xv.x + xv.y + xv.z + xv.w;
    float ss = xv.x*xv.x + xv.y*xv.y + xv.z*xv.z + xv.w*xv.w;
    block_reduce2_128(s, ss);
    float mu  = s * (1.0f / 512.0f);
    float var = ss * (1.0f / 512.0f) - mu * mu;
    float rstd = rsqrtf(var + 1e-12f);
    float4 gv = ((const float4*)g)[t];
    float4 bv = ((const float4*)b)[t];
    float4 o;
    o.x = (xv.x - mu) * rstd * gv.x + bv.x;
    o.y = (xv.y - mu) * rstd * gv.y + bv.y;
    o.z = (xv.z - mu) * rstd * gv.z + bv.z;
    o.w = (xv.w - mu) * rstd * gv.w + bv.w;
    ((float4*)g_h)[row * 128 + t] = o;
    __half2 h01 = __floats2half2_rn(o.x, o.y);
    __half2 h23 = __floats2half2_rn(o.z, o.w);
    uint2 u; u.x = *(uint32_t*)&h01; u.y = *(uint32_t*)&h23;
    ((uint2*)g_hh)[row * 128 + t] = u;
}

// ---------------------------------------------------------------------------
// fp16 GEMM via mma.sync.m16n8k16: C[M,N] = A[M,512] * Bt^T + bias
//   Tile 128(M) x 128(N), K-tile 64 halves (128B SW128 rows), 2-stage cp.async.
//   8 warps: 4(M) x 2(N) -> warp tile 32 x 64 (one 64-col head per warp).
//   mode 0: A=g_hh,  Bt=g_WtQKV, bias=g_bqkv, C=g_qkv, N=1536, featmap on n<1024
//   mode 1: A=g_ctxh,Bt=g_WtD,   bias=extB,   C=g_o,   N=512
// ---------------------------------------------------------------------------
#define STAGE_BYTES 32768            // A 16KB + B 16KB
#define GEMM_SMEM   (2 * STAGE_BYTES)

__global__ __launch_bounds__(256) void gemm_f16(int mode, const float* __restrict__ extB) {
    const __half* A; const __half* Bt; const float* bias; float* C; int N, fuse;
    if (mode == 0) { A = g_hh;   Bt = g_WtQKV; bias = g_bqkv; C = g_qkv; N = 1536; fuse = 1; }
    else           { A = g_ctxh; Bt = g_WtD;   bias = extB;   C = g_o;   N = 512;  fuse = 0; }

    extern __shared__ char sm[];
    int tid = threadIdx.x, warp = tid >> 5, lane = tid & 31;
    int wm = warp >> 1, wn = warp & 1;
    int gid = lane >> 2, tig = lane & 3;
    int m0 = blockIdx.y * 128, n0 = blockIdx.x * 128;
    uint32_t sb = smem_u32(sm);

    float acc[2][8][4];
#pragma unroll
    for (int i = 0; i < 2; i++)
#pragma unroll
        for (int j = 0; j < 8; j++)
#pragma unroll
            for (int k = 0; k < 4; k++) acc[i][j][k] = 0.0f;

    auto load_stage = [&](int s, int kt) {
        uint32_t ad = sb + s * STAGE_BYTES;
        const __half* Ag = A + (size_t)m0 * 512 + kt * 64;
#pragma unroll
        for (int i = 0; i < 4; i++) {
            int idx = i * 256 + tid;
            int r = idx >> 3, c = idx & 7;
            CPASYNC16(ad + SWZ(r * 128 + c * 16), Ag + (size_t)r * 512 + c * 8);
        }
        uint32_t bd = ad + 16384;
        const __half* Bg = Bt + (size_t)n0 * 512 + kt * 64;
#pragma unroll
        for (int i = 0; i < 4; i++) {
            int idx = i * 256 + tid;
            int r = idx >> 3, c = idx & 7;
            CPASYNC16(bd + SWZ(r * 128 + c * 16), Bg + (size_t)r * 512 + c * 8);
        }
        CP_COMMIT();
    };

    load_stage(0, 0);
    for (int kt = 0; kt < 8; ++kt) {
        int p = kt & 1;
        CP_WAIT0();
        __syncthreads();
        if (kt < 7) load_stage(1 - p, kt + 1);

        const char* aP = sm + p * STAGE_BYTES;
        const char* bP = aP + 16384;
#pragma unroll
        for (int ks = 0; ks < 4; ks++) {
            uint32_t bfr[8][2];
#pragma unroll
            for (int j = 0; j < 8; j++) {
                int col = 64 * wn + 8 * j + gid;
                bfr[j][0] = *(const uint32_t*)(bP + SWZ(col * 128 + ks * 32 + tig * 4));
                bfr[j][1] = *(const uint32_t*)(bP + SWZ(col * 128 + ks * 32 + 16 + tig * 4));
            }
#pragma unroll
            for (int i = 0; i < 2; i++) {
                int ra = 32 * wm + 16 * i + gid;
                uint32_t a0 = *(const uint32_t*)(aP + SWZ(ra * 128 + ks * 32 + tig * 4));
                uint32_t a1 = *(const uint32_t*)(aP + SWZ((ra + 8) * 128 + ks * 32 + tig * 4));
                uint32_t a2 = *(const uint32_t*)(aP + SWZ(ra * 128 + ks * 32 + 16 + tig * 4));
                uint32_t a3 = *(const uint32_t*)(aP + SWZ((ra + 8) * 128 + ks * 32 + 16 + tig * 4));
#pragma unroll
                for (int j = 0; j < 8; j++) {
                    asm volatile(
                        "mma.sync.aligned.m16n8k16.row.col.f32.f16.f16.f32 "
                        "{%0,%1,%2,%3},{%4,%5,%6,%7},{%8,%9},{%0,%1,%2,%3};"
                        : "+f"(acc[i][j][0]), "+f"(acc[i][j][1]),
                          "+f"(acc[i][j][2]), "+f"(acc[i][j][3])
                        : "r"(a0), "r"(a1), "r"(a2), "r"(a3),
                          "r"(bfr[j][0]), "r"(bfr[j][1]));
                }
            }
        }
    }

    // Epilogue: bias (+ fused ELU + per-head L2 norm for q,k) then store fp32
    float bv[16];
#pragma unroll
    for (int j = 0; j < 8; j++) {
        int col = n0 + 64 * wn + 8 * j + 2 * tig;
        bv[2*j]   = __ldg(bias + col);
        bv[2*j+1] = __ldg(bias + col + 1);
    }
    bool dof = fuse && (n0 + 64 * wn) < 1024;
#pragma unroll
    for (int i = 0; i < 2; i++) {
#pragma unroll
        for (int hr = 0; hr < 2; hr++) {
            float v[16];
#pragma unroll
            for (int j = 0; j < 8; j++) {
                v[2*j]   = acc[i][j][2*hr]     + bv[2*j];
                v[2*j+1] = acc[i][j][2*hr + 1] + bv[2*j+1];
            }
            if (dof) {
                float ss = 0.0f;
#pragma unroll
                for (int t = 0; t < 16; t++) {
                    v[t] = v[t] > 0.0f ? v[t] : expm1f(v[t]);
                    ss += v[t] * v[t];
                }
                ss += __shfl_xor_sync(0xffffffffu, ss, 1);
                ss += __shfl_xor_sync(0xffffffffu, ss, 2);
                float rn = rsqrtf(ss);
#pragma unroll
                for (int t = 0; t < 16; t++) v[t] *= rn;
            }
            int row = m0 + 32 * wm + 16 * i + 8 * hr + gid;
            float* cp = C + (size_t)row * N + n0 + 64 * wn + 2 * tig;
#pragma unroll
            for (int j = 0; j < 8; j++)
                *(float2*)(cp + 8 * j) = make_float2(v[2*j], v[2*j+1]);
        }
    }
}

// ---------------------------------------------------------------------------
// kv[b,h,d,e] = sum_s kn[s,d] * v[s,e]   (one block per (b,h))
// ---------------------------------------------------------------------------
__global__ __launch_bounds__(256) void kv_kernel() {
    int bh = blockIdx.x;
    int b = bh >> 3, h = bh & 7;
    __shared__ float kn_s[40 * 64];
    __shared__ float v_s [40 * 64];
    int tid = threadIdx.x;
    int d0 = (tid >> 4) << 2, e0 = (tid & 15) << 2;
    const float* base = g_qkv + (size_t)b * 200 * 1536 + h * 64;
    float acc[4][4];
#pragma unroll
    for (int i = 0; i < 4; i++)
#pragma unroll
        for (int j = 0; j < 4; j++) acc[i][j] = 0.0f;

    for (int st = 0; st < 5; ++st) {
        __syncthreads();
        for (int i = tid; i < 40 * 16; i += 256) {
            int r = i >> 4, nc = (i & 15) << 2;
            size_t off = (size_t)(st * 40 + r) * 1536 + nc;
            *(float4*)(kn_s + r * 64 + nc) = *(const float4*)(base + 512  + off);
            *(float4*)(v_s  + r * 64 + nc) = *(const float4*)(base + 1024 + off);
        }
        __syncthreads();
#pragma unroll 8
        for (int s = 0; s < 40; s++) {
            float4 kk = *(float4*)(kn_s + s * 64 + d0);
            float4 vv = *(float4*)(v_s  + s * 64 + e0);
            float ka[4] = {kk.x, kk.y, kk.z, kk.w};
            float va[4] = {vv.x, vv.y, vv.z, vv.w};
#pragma unroll
            for (int i = 0; i < 4; i++)
#pragma unroll
                for (int j = 0; j < 4; j++) acc[i][j] += ka[i] * va[j];
        }
    }
    float* o = g_kv + (size_t)bh * 4096;
#pragma unroll
    for (int i = 0; i < 4; i++)
        *(float4*)(o + (d0 + i) * 64 + e0) =
            make_float4(acc[i][0], acc[i][1], acc[i][2], acc[i][3]);
}

// ---------------------------------------------------------------------------
// ctx[b,s,h,e] = fp16( (1/8) * sum_d qn[s,d] * kv[d,e] )
// ---------------------------------------------------------------------------
__global__ __launch_bounds__(256) void ctx_kernel() {
    int bh = blockIdx.x;
    int b = bh >> 3, h = bh & 7;
    __shared__ float kvs[64 * 64];
    __shared__ float qns[64 * 68];
    int tid = threadIdx.x;
    for (int i = tid; i < 64 * 16; i += 256) {
        int d = i >> 4, nc = (i & 15) << 2;
        *(float4*)(kvs + d * 64 + nc) = *(const float4*)(g_kv + (size_t)bh * 4096 + d * 64 + nc);
    }
    const float* qbase = g_qkv + (size_t)b * 200 * 1536 + h * 64;
    __half* obase = g_ctxh + (size_t)b * 200 * 512 + h * 64;

    for (int c = 0; c < 4; c++) {
        int cs = min(64, 200 - c * 64);
        __syncthreads();
        for (int i = tid; i < cs * 16; i += 256) {
            int r = i >> 4, nc = (i & 15) << 2;
            *(float4*)(qns + r * 68 + nc) =
                *(const float4*)(qbase + (size_t)(c * 64 + r) * 1536 + nc);
        }
        __syncthreads();
        int sl = (tid >> 4) << 2, e0 = (tid & 15) << 2;
        if (sl < cs) {
            float acc[4][4];
#pragma unroll
            for (int i = 0; i < 4; i++)
#pragma unroll
                for (int j = 0; j < 4; j++) acc[i][j] = 0.0f;
#pragma unroll 8
            for (int d = 0; d < 64; d++) {
                float4 kv4 = *(float4*)(kvs + d * 64 + e0);
#pragma unroll
                for (int i = 0; i < 4; i++) {
                    float q = qns[(sl + i) * 68 + d];
                    acc[i][0] += q * kv4.x; acc[i][1] += q * kv4.y;
                    acc[i][2] += q * kv4.z; acc[i][3] += q * kv4.w;
                }
            }
#pragma unroll
            for (int i = 0; i < 4; i++) {
                __half2 h01 = __floats2half2_rn(acc[i][0] * 0.125f, acc[i][1] * 0.125f);
                __half2 h23 = __floats2half2_rn(acc[i][2] * 0.125f, acc[i][3] * 0.125f);
                uint2 u; u.x = *(uint32_t*)&h01; u.y = *(uint32_t*)&h23;
                *(uint2*)(obase + (size_t)(c * 64 + sl + i) * 512 + e0) = u;
            }
        }
    }
}

// ---------------------------------------------------------------------------
// out = LayerNorm(g_o + g_h)
// ---------------------------------------------------------------------------
__global__ void final_ln(const float* __restrict__ g, const float* __restrict__ bv_,
                         float* __restrict__ out) {
    size_t row = blockIdx.x;
    int t = threadIdx.x;
    float4 ov = ((const float4*)g_o)[row * 128 + t];
    float4 hv = ((const float4*)g_h)[row * 128 + t];
    ov.x += hv.x; ov.y += hv.y; ov.z += hv.z; ov.w += hv.w;
    float s  = ov.x + ov.y + ov.z + ov.w;
    float ss = ov.x*ov.x + ov.y*ov.y + ov.z*ov.z + ov.w*ov.w;
    block_reduce2_128(s, ss);
    float mu  = s * (1.0f / 512.0f);
    float var = ss * (1.0f / 512.0f) - mu * mu;
    float rstd = rsqrtf(var + 1e-12f);
    float4 gv = ((const float4*)g)[t];
    float4 bb = ((const float4*)bv_)[t];
    float4 o;
    o.x = (ov.x - mu) * rstd * gv.x + bb.x;
    o.y = (ov.y - mu) * rstd * gv.y + bb.y;
    o.z = (ov.z - mu) * rstd * gv.z + bb.z;
    o.w = (ov.w - mu) * rstd * gv.w + bb.w;
    ((float4*)out)[row * 128 + t] = o;
}

// ---------------------------------------------------------------------------
// Launch
// ---------------------------------------------------------------------------
extern "C" void kernel_launch(void* const* d_in, const int* in_sizes, int n_in,
                              void* d_out, int out_size) {
    const float* input = (const float*)d_in[0];
    const float* pos   = (const float*)d_in[1];
    // d_in[2] = attention_mask (unused by LinMHA)
    const float* Wq = (const float*)d_in[3];
    const float* bq = (const float*)d_in[4];
    const float* Wk = (const float*)d_in[5];
    const float* bk = (const float*)d_in[6];
    const float* Wv = (const float*)d_in[7];
    const float* bv = (const float*)d_in[8];
    const float* Wd = (const float*)d_in[9];
    const float* bd = (const float*)d_in[10];
    const float* lng = (const float*)d_in[11];
    const float* lnb = (const float*)d_in[12];
    float* out = (float*)d_out;

    static bool attr_set = false;
    if (!attr_set) {
        cudaFuncSetAttribute(gemm_f16, cudaFuncAttributeMaxDynamicSharedMemorySize, GEMM_SMEM);
        attr_set = true;
    }

    pack_wt<<<dim3(16, 16, 4), dim3(32, 8)>>>(Wq, Wk, Wv, Wd);
    pack_bias<<<2, 256>>>(bq, bk, bv);
    add_ln<<<MM, 128>>>(input, pos, lng, lnb);
    gemm_f16<<<dim3(12, 800), 256, GEMM_SMEM>>>(0, nullptr);   // QKV + featmap
    kv_kernel<<<4096, 256>>>();
    ctx_kernel<<<4096, 256>>>();
    gemm_f16<<<dim3(4, 800), 256, GEMM_SMEM>>>(1, bd);         // output proj
    final_ln<<<MM, 128>>>(lng, lnb, out);
}

// round 4
// speedup vs baseline: 2.1842x; 1.1008x over previous
#include <cuda_runtime.h>
#include <cuda_fp16.h>
#include <cstdint>

#define BB 512
#define SS 200
#define DD 512
#define HH 8
#define DHH 64
#define MM (BB*SS)          // 102400 rows

// ---------------------------------------------------------------------------
// Scratch (device globals; no allocations anywhere)
// ---------------------------------------------------------------------------
__device__ float  g_h   [(size_t)MM * DD];        // fp32 LN(x) for residual
__device__ __half g_hh  [(size_t)MM * DD];        // fp16 LN(x) for GEMM A
__device__ __half g_qkv [(size_t)MM * 3 * DD];    // fp16 [M,1536] q|k|v (featmap fused)
__device__ float  g_kv  [(size_t)BB * HH * DHH * DHH];
__device__ __half g_ctxh[(size_t)MM * DD];        // fp16 ctx for GEMM2 A
__device__ float  g_o   [(size_t)MM * DD];
__device__ __half g_WtQKV[(size_t)3 * DD * DD];   // [1536][512] = W^T fp16
__device__ __half g_WtD  [(size_t)DD * DD];       // [512][512]  = Wd^T fp16
__device__ float  g_bqkv [3 * DD];

// ---------------------------------------------------------------------------
// Helpers
// ---------------------------------------------------------------------------
__device__ __forceinline__ uint32_t smem_u32(const void* p) {
    uint32_t a;
    asm("{ .reg .u64 t; cvta.to.shared.u64 t, %1; cvt.u32.u64 %0, t; }"
        : "=r"(a) : "l"(p));
    return a;
}
#define CPASYNC16(dst, src) \
    asm volatile("cp.async.cg.shared.global [%0], [%1], 16;" :: "r"(dst), "l"(src) : "memory")
#define CP_COMMIT() asm volatile("cp.async.commit_group;" ::: "memory")
#define CP_WAIT0()  asm volatile("cp.async.wait_group 0;" ::: "memory")
#define SWZ(o) ((o) ^ (((o) >> 3) & 0x70))
#define LDSM4(r0, r1, r2, r3, a) \
    asm volatile("ldmatrix.sync.aligned.m8n8.x4.shared.b16 {%0,%1,%2,%3}, [%4];" \
                 : "=r"(r0), "=r"(r1), "=r"(r2), "=r"(r3) : "r"(a))

// ---------------------------------------------------------------------------
// Weight transpose + fp16: Wt[n][k] = fp16(W[k][n]). grid (16,16,4), block (32,8)
// ---------------------------------------------------------------------------
__global__ void pack_wt(const float* __restrict__ Wq, const float* __restrict__ Wk,
                        const float* __restrict__ Wv, const float* __restrict__ Wd) {
    __shared__ float t[32][33];
    int z = blockIdx.z;
    const float* W = z == 0 ? Wq : z == 1 ? Wk : z == 2 ? Wv : Wd;
    int x0 = blockIdx.x * 32, y0 = blockIdx.y * 32;
    int tx = threadIdx.x, ty = threadIdx.y;
#pragma unroll
    for (int i = 0; i < 32; i += 8)
        t[ty + i][tx] = W[(size_t)(y0 + ty + i) * 512 + x0 + tx];
    __syncthreads();
    __half* dst = (z < 3) ? (g_WtQKV + (size_t)z * 512 * 512) : g_WtD;
#pragma unroll
    for (int i = 0; i < 32; i += 8)
        dst[(size_t)(x0 + ty + i) * 512 + y0 + tx] = __float2half_rn(t[tx][ty + i]);
}

__global__ void pack_bias(const float* __restrict__ bq, const float* __restrict__ bk,
                          const float* __restrict__ bv) {
    int i = blockIdx.x * 256 + threadIdx.x;
    if (i < 512) { g_bqkv[i] = bq[i]; g_bqkv[512 + i] = bk[i]; g_bqkv[1024 + i] = bv[i]; }
}

// ---------------------------------------------------------------------------
// Block reduce (128 threads, 2 values)
// ---------------------------------------------------------------------------
__device__ __forceinline__ void block_reduce2_128(float& a, float& b) {
#pragma unroll
    for (int o = 16; o > 0; o >>= 1) {
        a += __shfl_xor_sync(0xffffffffu, a, o);
        b += __shfl_xor_sync(0xffffffffu, b, o);
    }
    __shared__ float sa[4], sb[4];
    int w = threadIdx.x >> 5, l = threadIdx.x & 31;
    if (l == 0) { sa[w] = a; sb[w] = b; }
    __syncthreads();
    a = sa[0] + sa[1] + sa[2] + sa[3];
    b = sb[0] + sb[1] + sb[2] + sb[3];
}

// ---------------------------------------------------------------------------
// h = LayerNorm(input + pos); write fp32 (residual) + fp16 (GEMM A)
// ---------------------------------------------------------------------------
__global__ void add_ln(const float* __restrict__ x, const float* __restrict__ p,
                       const float* __restrict__ g, const float* __restrict__ b) {
    size_t row = blockIdx.x;
    int t = threadIdx.x;
    float4 xv = ((const float4*)x)[row * 128 + t];
    float4 pv = ((const float4*)p)[row * 128 + t];
    xv.x += pv.x; xv.y += pv.y; xv.z += pv.z; xv.w += pv.w;
    float s  = xv.x + xv.y + xv.z + xv.w;
    float ss = xv.x*xv.x + xv.y*xv.y + xv.z*xv.z + xv.w*xv.w;
    block_reduce2_128(s, ss);
    float mu  = s * (1.0f / 512.0f);
    float var = ss * (1.0f / 512.0f) - mu * mu;
    float rstd = rsqrtf(var + 1e-12f);
    float4 gv = ((const float4*)g)[t];
    float4 bv = ((const float4*)b)[t];
    float4 o;
    o.x = (xv.x - mu) * rstd * gv.x + bv.x;
    o.y = (xv.y - mu) * rstd * gv.y + bv.y;
    o.z = (xv.z - mu) * rstd * gv.z + bv.z;
    o.w = (xv.w - mu) * rstd * gv.w + bv.w;
    ((float4*)g_h)[row * 128 + t] = o;
    __half2 h01 = __floats2half2_rn(o.x, o.y);
    __half2 h23 = __floats2half2_rn(o.z, o.w);
    uint2 u; u.x = *(uint32_t*)&h01; u.y = *(uint32_t*)&h23;
    ((uint2*)g_hh)[row * 128 + t] = u;
}

// ---------------------------------------------------------------------------
// fp16 GEMM via mma.sync.m16n8k16 + ldmatrix: C = A[M,512] * Bt^T + bias
//   Tile 128(M) x 128(N), K-tile 64 halves, 2-stage cp.async, SW128 smem.
//   8 warps: 4(M) x 2(N) -> warp tile 32 x 64 (one 64-col head per warp).
//   mode 0: A=g_hh,  Bt=g_WtQKV, C=g_qkv (fp16), N=1536, featmap on n<1024
//   mode 1: A=g_ctxh,Bt=g_WtD,   C=g_o   (fp32), N=512
// ---------------------------------------------------------------------------
#define STAGE_BYTES 32768            // A 16KB + B 16KB
#define GEMM_SMEM   (2 * STAGE_BYTES)

__global__ void __launch_bounds__(256, 2) gemm_f16(int mode, const float* __restrict__ extB) {
    const __half* A; const __half* Bt; const float* bias; int N, fuse;
    if (mode == 0) { A = g_hh;   Bt = g_WtQKV; bias = g_bqkv; N = 1536; fuse = 1; }
    else           { A = g_ctxh; Bt = g_WtD;   bias = extB;   N = 512;  fuse = 0; }

    extern __shared__ char sm[];
    int tid = threadIdx.x, warp = tid >> 5, lane = tid & 31;
    int wm = warp >> 1, wn = warp & 1;
    int gid = lane >> 2, tig = lane & 3;
    int m0 = blockIdx.y * 128, n0 = blockIdx.x * 128;
    uint32_t sb = smem_u32(sm);

    // Per-thread ldmatrix address components (stage-relative)
    // A: matrices ordered a0(m0-7,k0-7) a1(m8,k0) a2(m0,k8) a3(m8,k8)
    uint32_t aOff[2], aXr[2];
    uint32_t aKb = (lane >> 4) * 16;                       // k-byte offset (0|16)
    {
        int jlo = (lane >> 3) & 1, i = lane & 7;
#pragma unroll
        for (int ii = 0; ii < 2; ii++) {
            int m = 32 * wm + 16 * ii + jlo * 8 + i;
            aOff[ii] = m * 128;
            aXr[ii]  = (m & 7) * 16;
        }
    }
    // B: per x4 group g covers n-tiles (2g, 2g+1); matrices (j0,k0)(j0,k8)(j1,k0)(j1,k8)
    uint32_t bOff[4], bXr[4];
    uint32_t bKb = ((lane >> 3) & 1) * 16;
    {
        int i = lane & 7;
#pragma unroll
        for (int g = 0; g < 4; g++) {
            int n = 64 * wn + 8 * (2 * g + (lane >> 4)) + i;
            bOff[g] = 16384 + n * 128;
            bXr[g]  = (n & 7) * 16;
        }
    }

    float acc[2][8][4];
#pragma unroll
    for (int i = 0; i < 2; i++)
#pragma unroll
        for (int j = 0; j < 8; j++)
#pragma unroll
            for (int k = 0; k < 4; k++) acc[i][j][k] = 0.0f;

    auto load_stage = [&](int s, int kt) {
        uint32_t ad = sb + s * STAGE_BYTES;
        const __half* Ag = A + (size_t)m0 * 512 + kt * 64;
#pragma unroll
        for (int i = 0; i < 4; i++) {
            int idx = i * 256 + tid;
            int r = idx >> 3, c = idx & 7;
            CPASYNC16(ad + SWZ(r * 128 + c * 16), Ag + (size_t)r * 512 + c * 8);
        }
        uint32_t bd = ad + 16384;
        const __half* Bg = Bt + (size_t)n0 * 512 + kt * 64;
#pragma unroll
        for (int i = 0; i < 4; i++) {
            int idx = i * 256 + tid;
            int r = idx >> 3, c = idx & 7;
            CPASYNC16(bd + SWZ(r * 128 + c * 16), Bg + (size_t)r * 512 + c * 8);
        }
        CP_COMMIT();
    };

    load_stage(0, 0);
    for (int kt = 0; kt < 8; ++kt) {
        int p = kt & 1;
        CP_WAIT0();
        __syncthreads();
        if (kt < 7) load_stage(1 - p, kt + 1);

        uint32_t stg = sb + p * STAGE_BYTES;
#pragma unroll
        for (int ks = 0; ks < 4; ks++) {
            uint32_t kbyte = ks * 32;
            uint32_t bfr[8][2];
#pragma unroll
            for (int g = 0; g < 4; g++) {
                uint32_t addr = stg + bOff[g] + ((kbyte + bKb) ^ bXr[g]);
                LDSM4(bfr[2*g][0], bfr[2*g][1], bfr[2*g+1][0], bfr[2*g+1][1], addr);
            }
#pragma unroll
            for (int i = 0; i < 2; i++) {
                uint32_t a0, a1, a2, a3;
                uint32_t addr = stg + aOff[i] + ((kbyte + aKb) ^ aXr[i]);
                LDSM4(a0, a1, a2, a3, addr);
#pragma unroll
                for (int j = 0; j < 8; j++) {
                    asm volatile(
                        "mma.sync.aligned.m16n8k16.row.col.f32.f16.f16.f32 "
                        "{%0,%1,%2,%3},{%4,%5,%6,%7},{%8,%9},{%0,%1,%2,%3};"
                        : "+f"(acc[i][j][0]), "+f"(acc[i][j][1]),
                          "+f"(acc[i][j][2]), "+f"(acc[i][j][3])
                        : "r"(a0), "r"(a1), "r"(a2), "r"(a3),
                          "r"(bfr[j][0]), "r"(bfr[j][1]));
                }
            }
        }
    }

    // Epilogue: bias (+ fused ELU + per-head L2 norm for q,k), store
    float bv[16];
#pragma unroll
    for (int j = 0; j < 8; j++) {
        int col = n0 + 64 * wn + 8 * j + 2 * tig;
        bv[2*j]   = __ldg(bias + col);
        bv[2*j+1] = __ldg(bias + col + 1);
    }
    bool dof = fuse && (n0 + 64 * wn) < 1024;
#pragma unroll
    for (int i = 0; i < 2; i++) {
#pragma unroll
        for (int hr = 0; hr < 2; hr++) {
            float v[16];
#pragma unroll
            for (int j = 0; j < 8; j++) {
                v[2*j]   = acc[i][j][2*hr]     + bv[2*j];
                v[2*j+1] = acc[i][j][2*hr + 1] + bv[2*j+1];
            }
            if (dof) {
                float ss = 0.0f;
#pragma unroll
                for (int t = 0; t < 16; t++) {
                    v[t] = v[t] > 0.0f ? v[t] : expm1f(v[t]);
                    ss += v[t] * v[t];
                }
                ss += __shfl_xor_sync(0xffffffffu, ss, 1);
                ss += __shfl_xor_sync(0xffffffffu, ss, 2);
                float rn = rsqrtf(ss);
#pragma unroll
                for (int t = 0; t < 16; t++) v[t] *= rn;
            }
            int row = m0 + 32 * wm + 16 * i + 8 * hr + gid;
            if (mode == 0) {
                __half* cp = g_qkv + (size_t)row * 1536 + n0 + 64 * wn + 2 * tig;
#pragma unroll
                for (int j = 0; j < 8; j++) {
                    __half2 hv = __floats2half2_rn(v[2*j], v[2*j+1]);
                    *(uint32_t*)(cp + 8 * j) = *(uint32_t*)&hv;
                }
            } else {
                float* cp = g_o + (size_t)row * 512 + n0 + 64 * wn + 2 * tig;
#pragma unroll
                for (int j = 0; j < 8; j++)
                    *(float2*)(cp + 8 * j) = make_float2(v[2*j], v[2*j+1]);
            }
        }
    }
}

// ---------------------------------------------------------------------------
// kv[b,h,d,e] = sum_s kn[s,d] * v[s,e]   (one block per (b,h)); fp16 in, fp32 acc
// ---------------------------------------------------------------------------
__global__ __launch_bounds__(256) void kv_kernel() {
    int bh = blockIdx.x;
    int b = bh >> 3, h = bh & 7;
    __shared__ float kn_s[40 * 64];
    __shared__ float v_s [40 * 64];
    int tid = threadIdx.x;
    int d0 = (tid >> 4) << 2, e0 = (tid & 15) << 2;
    const __half* base = g_qkv + (size_t)b * 200 * 1536 + h * 64;
    float acc[4][4];
#pragma unroll
    for (int i = 0; i < 4; i++)
#pragma unroll
        for (int j = 0; j < 4; j++) acc[i][j] = 0.0f;

    for (int st = 0; st < 5; ++st) {
        __syncthreads();
        for (int i = tid; i < 40 * 8; i += 256) {
            int r = i >> 3, c = (i & 7) * 8;
            size_t off = (size_t)(st * 40 + r) * 1536 + c;
            uint4 uk = *(const uint4*)(base + 512  + off);
            uint4 uv = *(const uint4*)(base + 1024 + off);
            const __half2* hk = (const __half2*)&uk;
            const __half2* hv = (const __half2*)&uv;
#pragma unroll
            for (int q = 0; q < 4; q++) {
                float2 fk = __half22float2(hk[q]);
                float2 fv = __half22float2(hv[q]);
                kn_s[r * 64 + c + 2*q]     = fk.x;
                kn_s[r * 64 + c + 2*q + 1] = fk.y;
                v_s [r * 64 + c + 2*q]     = fv.x;
                v_s [r * 64 + c + 2*q + 1] = fv.y;
            }
        }
        __syncthreads();
#pragma unroll 8
        for (int s = 0; s < 40; s++) {
            float4 kk = *(float4*)(kn_s + s * 64 + d0);
            float4 vv = *(float4*)(v_s  + s * 64 + e0);
            float ka[4] = {kk.x, kk.y, kk.z, kk.w};
            float va[4] = {vv.x, vv.y, vv.z, vv.w};
#pragma unroll
            for (int i = 0; i < 4; i++)
#pragma unroll
                for (int j = 0; j < 4; j++) acc[i][j] += ka[i] * va[j];
        }
    }
    float* o = g_kv + (size_t)bh * 4096;
#pragma unroll
    for (int i = 0; i < 4; i++)
        *(float4*)(o + (d0 + i) * 64 + e0) =
            make_float4(acc[i][0], acc[i][1], acc[i][2], acc[i][3]);
}

// ---------------------------------------------------------------------------
// ctx[b,s,h,e] = fp16( (1/8) * sum_d qn[s,d] * kv[d,e] )
// ---------------------------------------------------------------------------
__global__ __launch_bounds__(256) void ctx_kernel() {
    int bh = blockIdx.x;
    int b = bh >> 3, h = bh & 7;
    __shared__ float kvs[64 * 64];
    __shared__ float qns[64 * 68];
    int tid = threadIdx.x;
    for (int i = tid; i < 64 * 16; i += 256) {
        int d = i >> 4, nc = (i & 15) << 2;
        *(float4*)(kvs + d * 64 + nc) = *(const float4*)(g_kv + (size_t)bh * 4096 + d * 64 + nc);
    }
    const __half* qbase = g_qkv + (size_t)b * 200 * 1536 + h * 64;
    __half* obase = g_ctxh + (size_t)b * 200 * 512 + h * 64;

    for (int c = 0; c < 4; c++) {
        int cs = min(64, 200 - c * 64);
        __syncthreads();
        for (int i = tid; i < cs * 8; i += 256) {
            int r = i >> 3, nc = (i & 7) * 8;
            uint4 uq = *(const uint4*)(qbase + (size_t)(c * 64 + r) * 1536 + nc);
            const __half2* hq = (const __half2*)&uq;
#pragma unroll
            for (int q = 0; q < 4; q++) {
                float2 f = __half22float2(hq[q]);
                qns[r * 68 + nc + 2*q]     = f.x;
                qns[r * 68 + nc + 2*q + 1] = f.y;
            }
        }
        __syncthreads();
        int sl = (tid >> 4) << 2, e0 = (tid & 15) << 2;
        if (sl < cs) {
            float acc[4][4];
#pragma unroll
            for (int i = 0; i < 4; i++)
#pragma unroll
                for (int j = 0; j < 4; j++) acc[i][j] = 0.0f;
#pragma unroll 8
            for (int d = 0; d < 64; d++) {
                float4 kv4 = *(float4*)(kvs + d * 64 + e0);
#pragma unroll
                for (int i = 0; i < 4; i++) {
                    float q = qns[(sl + i) * 68 + d];
                    acc[i][0] += q * kv4.x; acc[i][1] += q * kv4.y;
                    acc[i][2] += q * kv4.z; acc[i][3] += q * kv4.w;
                }
            }
#pragma unroll
            for (int i = 0; i < 4; i++) {
                __half2 h01 = __floats2half2_rn(acc[i][0] * 0.125f, acc[i][1] * 0.125f);
                __half2 h23 = __floats2half2_rn(acc[i][2] * 0.125f, acc[i][3] * 0.125f);
                uint2 u; u.x = *(uint32_t*)&h01; u.y = *(uint32_t*)&h23;
                *(uint2*)(obase + (size_t)(c * 64 + sl + i) * 512 + e0) = u;
            }
        }
    }
}

// ---------------------------------------------------------------------------
// out = LayerNorm(g_o + g_h)
// ---------------------------------------------------------------------------
__global__ void final_ln(const float* __restrict__ g, const float* __restrict__ bv_,
                         float* __restrict__ out) {
    size_t row = blockIdx.x;
    int t = threadIdx.x;
    float4 ov = ((const float4*)g_o)[row * 128 + t];
    float4 hv = ((const float4*)g_h)[row * 128 + t];
    ov.x += hv.x; ov.y += hv.y; ov.z += hv.z; ov.w += hv.w;
    float s  = ov.x + ov.y + ov.z + ov.w;
    float ss = ov.x*ov.x + ov.y*ov.y + ov.z*ov.z + ov.w*ov.w;
    block_reduce2_128(s, ss);
    float mu  = s * (1.0f / 512.0f);
    float var = ss * (1.0f / 512.0f) - mu * mu;
    float rstd = rsqrtf(var + 1e-12f);
    float4 gv = ((const float4*)g)[t];
    float4 bb = ((const float4*)bv_)[t];
    float4 o;
    o.x = (ov.x - mu) * rstd * gv.x + bb.x;
    o.y = (ov.y - mu) * rstd * gv.y + bb.y;
    o.z = (ov.z - mu) * rstd * gv.z + bb.z;
    o.w = (ov.w - mu) * rstd * gv.w + bb.w;
    ((float4*)out)[row * 128 + t] = o;
}

// ---------------------------------------------------------------------------
// Launch
// ---------------------------------------------------------------------------
extern "C" void kernel_launch(void* const* d_in, const int* in_sizes, int n_in,
                              void* d_out, int out_size) {
    const float* input = (const float*)d_in[0];
    const float* pos   = (const float*)d_in[1];
    // d_in[2] = attention_mask (unused by LinMHA)
    const float* Wq = (const float*)d_in[3];
    const float* bq = (const float*)d_in[4];
    const float* Wk = (const float*)d_in[5];
    const float* bk = (const float*)d_in[6];
    const float* Wv = (const float*)d_in[7];
    const float* bv = (const float*)d_in[8];
    const float* Wd = (const float*)d_in[9];
    const float* bd = (const float*)d_in[10];
    const float* lng = (const float*)d_in[11];
    const float* lnb = (const float*)d_in[12];
    float* out = (float*)d_out;

    static bool attr_set = false;
    if (!attr_set) {
        cudaFuncSetAttribute(gemm_f16, cudaFuncAttributeMaxDynamicSharedMemorySize, GEMM_SMEM);
        attr_set = true;
    }

    pack_wt<<<dim3(16, 16, 4), dim3(32, 8)>>>(Wq, Wk, Wv, Wd);
    pack_bias<<<2, 256>>>(bq, bk, bv);
    add_ln<<<MM, 128>>>(input, pos, lng, lnb);
    gemm_f16<<<dim3(12, 800), 256, GEMM_SMEM>>>(0, nullptr);   // QKV + featmap
    kv_kernel<<<4096, 256>>>();
    ctx_kernel<<<4096, 256>>>();
    gemm_f16<<<dim3(4, 800), 256, GEMM_SMEM>>>(1, bd);         // output proj
    final_ln<<<MM, 128>>>(lng, lnb, out);
}